// round 10
// baseline (speedup 1.0000x reference)
#include <cuda_runtime.h>
#include <cuda_bf16.h>
#include <cstdint>

// Problem constants: B=4, L=4096, D=1024, H=16, HD=64, P=128, MAXLEN=4096

// ---------------- scratch (no cudaMalloc allowed) ----------------
__device__ float g_Q[16384L * 1024];   // Q = x@Wq^T (pre-RoPE)
__device__ float g_K[512L * 1024];     // K for l<128 per batch
__device__ float g_V[512L * 1024];     // V for l<128 per batch
// bf16 hi/lo splits (A reused for x then attention output O)
__device__ __align__(16) __nv_bfloat16 g_Ah[16384L * 1024];
__device__ __align__(16) __nv_bfloat16 g_Al[16384L * 1024];
__device__ __align__(16) __nv_bfloat16 g_Wqh[1024 * 1024];
__device__ __align__(16) __nv_bfloat16 g_Wql[1024 * 1024];
__device__ __align__(16) __nv_bfloat16 g_Woh[1024 * 1024];
__device__ __align__(16) __nv_bfloat16 g_Wol[1024 * 1024];
// projections, pre-split (proj_kernel outputs)
__device__ __align__(16) __nv_bfloat16 g_KPh[64L * 128 * 64]; // [bh][p][d]
__device__ __align__(16) __nv_bfloat16 g_KPl[64L * 128 * 64];
__device__ __align__(16) __nv_bfloat16 g_VTh[64L * 2 * 64 * 64]; // [bh][half][d][p&63]
__device__ __align__(16) __nv_bfloat16 g_VTl[64L * 2 * 64 * 64];

__device__ __forceinline__ uint32_t smem_u32(const void* p) {
    uint32_t a;
    asm("{ .reg .u64 t; cvta.to.shared.u64 t, %1; cvt.u32.u64 %0, t; }" : "=r"(a) : "l"(p));
    return a;
}
__device__ __forceinline__ void ldsm_x4(uint32_t* r, uint32_t addr) {
    asm volatile("ldmatrix.sync.aligned.m8n8.x4.shared.b16 {%0,%1,%2,%3}, [%4];"
                 : "=r"(r[0]), "=r"(r[1]), "=r"(r[2]), "=r"(r[3]) : "r"(addr));
}
__device__ __forceinline__ void mma_bf16(float* c, const uint32_t* a, const uint32_t* b) {
    asm volatile("mma.sync.aligned.m16n8k16.row.col.f32.bf16.bf16.f32 "
                 "{%0,%1,%2,%3}, {%4,%5,%6,%7}, {%8,%9}, {%0,%1,%2,%3};"
                 : "+f"(c[0]), "+f"(c[1]), "+f"(c[2]), "+f"(c[3])
                 : "r"(a[0]), "r"(a[1]), "r"(a[2]), "r"(a[3]), "r"(b[0]), "r"(b[1]));
}
__device__ __forceinline__ void cp16(uint32_t dst, const void* src) {
    asm volatile("cp.async.cg.shared.global [%0], [%1], 16;" :: "r"(dst), "l"(src) : "memory");
}
__device__ __forceinline__ uint32_t pack_hi(float a, float b) {
    return (uint32_t)__bfloat16_as_ushort(__float2bfloat16(a))
         | ((uint32_t)__bfloat16_as_ushort(__float2bfloat16(b)) << 16);
}
__device__ __forceinline__ uint32_t pack_lo(float a, float b) {
    float ra = a - __bfloat162float(__float2bfloat16(a));
    float rb = b - __bfloat162float(__float2bfloat16(b));
    return (uint32_t)__bfloat16_as_ushort(__float2bfloat16(ra))
         | ((uint32_t)__bfloat16_as_ushort(__float2bfloat16(rb)) << 16);
}

// ---------------- fp32 -> bf16 hi/lo split (elementwise) ----------------
__global__ __launch_bounds__(256)
void cvt_hilo(const float* __restrict__ A, __nv_bfloat16* __restrict__ H,
              __nv_bfloat16* __restrict__ L)
{
    long i = (long)blockIdx.x * 256 + threadIdx.x;
    float4 v = ((const float4*)A)[i];
    uint2 hp = make_uint2(pack_hi(v.x, v.y), pack_hi(v.z, v.w));
    uint2 lp = make_uint2(pack_lo(v.x, v.y), pack_lo(v.z, v.w));
    ((uint2*)H)[i] = hp;
    ((uint2*)L)[i] = lp;
}

// ============ pipelined HMMA GEMM (validated round 7) ============
#define HG2_STAGE 65536
#define HG2_SMEM  131072

__device__ __forceinline__ void hg2_load(uint32_t sbase, int tid,
    const __nv_bfloat16* b0, const __nv_bfloat16* b1,
    const __nv_bfloat16* b2, const __nv_bfloat16* b3, int kc)
{
#pragma unroll
    for (int arr = 0; arr < 4; arr++) {
        const __nv_bfloat16* bp = (arr == 0) ? b0 : (arr == 1) ? b1 : (arr == 2) ? b2 : b3;
        uint32_t aoff = sbase + arr * 16384;
#pragma unroll
        for (int q = 0; q < 4; q++) {
            int idx = q * 256 + tid;
            int row = idx >> 3, c = idx & 7;
            uint32_t dst = aoff + row * 128 + (((uint32_t)(c ^ (row & 7))) << 4);
            cp16(dst, bp + (long)row * 1024 + kc * 64 + c * 8);
        }
    }
    asm volatile("cp.async.commit_group;" ::: "memory");
}

__global__ __launch_bounds__(256)
void hmma_gemm2(const __nv_bfloat16* __restrict__ Ah, const __nv_bfloat16* __restrict__ Al,
                const __nv_bfloat16* __restrict__ Bh, const __nv_bfloat16* __restrict__ Bl,
                float* __restrict__ C)
{
    extern __shared__ __align__(128) char sm[];
    const uint32_t sb = smem_u32(sm);
    const int tid = threadIdx.x, lane = tid & 31, wid = tid >> 5;
    const int wm = wid & 3, wn = wid >> 2;
    const long tile_m = (long)blockIdx.y * 128;
    const long tile_n = (long)blockIdx.x * 128;

    const __nv_bfloat16* base0 = Ah + tile_m * 1024;
    const __nv_bfloat16* base1 = Al + tile_m * 1024;
    const __nv_bfloat16* base2 = Bh + tile_n * 1024;
    const __nv_bfloat16* base3 = Bl + tile_n * 1024;

    float acc[2][8][4];
#pragma unroll
    for (int mt = 0; mt < 2; mt++)
#pragma unroll
        for (int nt = 0; nt < 8; nt++)
#pragma unroll
            for (int e = 0; e < 4; e++) acc[mt][nt][e] = 0.f;

    const int arow = wm * 32 + (lane & 15);
    const int ac   = lane >> 4;
    const int brow = wn * 64 + ((lane >> 4) << 3) + (lane & 7);
    const int bc   = (lane >> 3) & 1;

    hg2_load(sb, tid, base0, base1, base2, base3, 0);

    for (int kc = 0; kc < 16; kc++) {
        if (kc < 15) {
            hg2_load(sb + ((kc + 1) & 1) * HG2_STAGE, tid, base0, base1, base2, base3, kc + 1);
            asm volatile("cp.async.wait_group 1;" ::: "memory");
        } else {
            asm volatile("cp.async.wait_group 0;" ::: "memory");
        }
        __syncthreads();

        const uint32_t sbase = sb + (kc & 1) * HG2_STAGE;
#pragma unroll
        for (int ks = 0; ks < 4; ks++) {
            uint32_t aHi[2][4], aLo[2][4], bf[8][2];
            const int cA = ks * 2 + ac;
#pragma unroll
            for (int mt = 0; mt < 2; mt++) {
                int r = arow + mt * 16;
                uint32_t ad = sbase + r * 128 + ((uint32_t)(cA ^ (r & 7)) << 4);
                ldsm_x4(aHi[mt], ad);
                ldsm_x4(aLo[mt], ad + 16384);
            }
            const int cB = ks * 2 + bc;
#pragma unroll
            for (int nt2 = 0; nt2 < 4; nt2++) {
                int r = brow + nt2 * 16;
                uint32_t bd = sbase + 32768 + r * 128 + ((uint32_t)(cB ^ (r & 7)) << 4);
                uint32_t t[4]; ldsm_x4(t, bd);
                bf[nt2 * 2][0] = t[0]; bf[nt2 * 2][1] = t[1];
                bf[nt2 * 2 + 1][0] = t[2]; bf[nt2 * 2 + 1][1] = t[3];
            }
#pragma unroll
            for (int mt = 0; mt < 2; mt++)
#pragma unroll
                for (int nt = 0; nt < 8; nt++)
                    mma_bf16(acc[mt][nt], aHi[mt], bf[nt]);
#pragma unroll
            for (int mt = 0; mt < 2; mt++)
#pragma unroll
                for (int nt = 0; nt < 8; nt++)
                    mma_bf16(acc[mt][nt], aLo[mt], bf[nt]);
#pragma unroll
            for (int nt2 = 0; nt2 < 4; nt2++) {
                int r = brow + nt2 * 16;
                uint32_t bd = sbase + 49152 + r * 128 + ((uint32_t)(cB ^ (r & 7)) << 4);
                uint32_t t[4]; ldsm_x4(t, bd);
                bf[nt2 * 2][0] = t[0]; bf[nt2 * 2][1] = t[1];
                bf[nt2 * 2 + 1][0] = t[2]; bf[nt2 * 2 + 1][1] = t[3];
            }
#pragma unroll
            for (int mt = 0; mt < 2; mt++)
#pragma unroll
                for (int nt = 0; nt < 8; nt++)
                    mma_bf16(acc[mt][nt], aHi[mt], bf[nt]);
        }
        __syncthreads();
    }

#pragma unroll
    for (int mt = 0; mt < 2; mt++) {
#pragma unroll
        for (int nt = 0; nt < 8; nt++) {
            long row0 = tile_m + wm * 32 + mt * 16 + (lane >> 2);
            long col  = tile_n + wn * 64 + nt * 8 + (lane & 3) * 2;
            *(float2*)(C + row0 * 1024 + col)       = make_float2(acc[mt][nt][0], acc[mt][nt][1]);
            *(float2*)(C + (row0 + 8) * 1024 + col) = make_float2(acc[mt][nt][2], acc[mt][nt][3]);
        }
    }
}

// ---------------- small SGEMM for K/V (first 128 rows per batch) ----------------
__global__ __launch_bounds__(256, 2)
void sgemm_tn(const float* __restrict__ A, const float* __restrict__ B,
              float* __restrict__ C,
              const float* __restrict__ B2, float* __restrict__ C2,
              long aGroupStride)
{
    if (blockIdx.z == 1) { B = B2; C = C2; }

    __shared__ float As[16][128];
    __shared__ float Bs[16][128];

    const int tid = threadIdx.x;
    const int tx = tid & 15;
    const int ty = tid >> 4;
    const long aTile = (long)blockIdx.y * aGroupStride;
    const long bTile = (long)blockIdx.x * 128 * 1024;

    float acc[8][8];
#pragma unroll
    for (int i = 0; i < 8; i++)
#pragma unroll
        for (int j = 0; j < 8; j++) acc[i][j] = 0.f;

    for (int k0 = 0; k0 < 1024; k0 += 16) {
#pragma unroll
        for (int t = 0; t < 2; t++) {
            int f = tid + t * 256;
            int row = f >> 2;
            int c4  = f & 3;
            float4 va = *(const float4*)(A + aTile + (long)row * 1024 + k0 + c4 * 4);
            As[c4 * 4 + 0][row] = va.x;
            As[c4 * 4 + 1][row] = va.y;
            As[c4 * 4 + 2][row] = va.z;
            As[c4 * 4 + 3][row] = va.w;
            float4 vb = *(const float4*)(B + bTile + (long)row * 1024 + k0 + c4 * 4);
            Bs[c4 * 4 + 0][row] = vb.x;
            Bs[c4 * 4 + 1][row] = vb.y;
            Bs[c4 * 4 + 2][row] = vb.z;
            Bs[c4 * 4 + 3][row] = vb.w;
        }
        __syncthreads();
#pragma unroll
        for (int kk = 0; kk < 16; kk++) {
            float a[8], b[8];
            *(float4*)&a[0] = *(const float4*)&As[kk][ty * 8];
            *(float4*)&a[4] = *(const float4*)&As[kk][ty * 8 + 4];
            *(float4*)&b[0] = *(const float4*)&Bs[kk][tx * 8];
            *(float4*)&b[4] = *(const float4*)&Bs[kk][tx * 8 + 4];
#pragma unroll
            for (int i = 0; i < 8; i++)
#pragma unroll
                for (int j = 0; j < 8; j++)
                    acc[i][j] += a[i] * b[j];
        }
        __syncthreads();
    }

#pragma unroll
    for (int i = 0; i < 8; i++) {
        long crow = (long)blockIdx.y * 128 + ty * 8 + i;
        long cbase = crow * 1024 + blockIdx.x * 128 + tx * 8;
        *(float4*)(C + cbase)     = make_float4(acc[i][0], acc[i][1], acc[i][2], acc[i][3]);
        *(float4*)(C + cbase + 4) = make_float4(acc[i][4], acc[i][5], acc[i][6], acc[i][7]);
    }
}

// ---------------- projection kernel: KP/VP in bf16 hi/lo ----------------
__global__ __launch_bounds__(128)
void proj_kernel(const float* __restrict__ Kb, const float* __restrict__ Vb,
                 const float* __restrict__ kpm, const float* __restrict__ vpm,
                 const float* __restrict__ fcos, const float* __restrict__ fsin,
                 __nv_bfloat16* __restrict__ KPh, __nv_bfloat16* __restrict__ KPl,
                 __nv_bfloat16* __restrict__ VTh, __nv_bfloat16* __restrict__ VTl)
{
    __shared__ float buf[128][64];
    const int bh = blockIdx.x;
    const int b = bh >> 4, h = bh & 15;
    const int tid = threadIdx.x;

    // ---- K pass (with RoPE) ----
    for (int idx = tid; idx < 128 * 64; idx += 128) {
        int l = idx >> 6, d = idx & 63;
        buf[l][d] = Kb[(long)(b * 128 + l) * 1024 + h * 64 + d];
    }
    __syncthreads();
    for (int idx = tid; idx < 128 * 32; idx += 128) {
        int l = idx >> 5, i = idx & 31;
        float c = fcos[l * 32 + i], s = fsin[l * 32 + i];
        float tr = buf[l][2 * i], ti = buf[l][2 * i + 1];
        buf[l][2 * i]     = tr * c - ti * s;
        buf[l][2 * i + 1] = tr * s + ti * c;
    }
    __syncthreads();
    {
        const int p = tid;
        float acc[64];
#pragma unroll
        for (int d = 0; d < 64; d++) acc[d] = 0.f;
        const float* kr = kpm + (long)p * 4096;
        for (int l = 0; l <= p; l++) {
            float cf = kr[l];
#pragma unroll
            for (int d = 0; d < 64; d++) acc[d] += cf * buf[l][d];
        }
        long dst = (long)bh * 8192 + (long)p * 64;
#pragma unroll
        for (int d = 0; d < 64; d += 2) {
            *(uint32_t*)(KPh + dst + d) = pack_hi(acc[d], acc[d + 1]);
            *(uint32_t*)(KPl + dst + d) = pack_lo(acc[d], acc[d + 1]);
        }
    }
    __syncthreads();

    // ---- V pass (no RoPE), transposed output ----
    for (int idx = tid; idx < 128 * 64; idx += 128) {
        int l = idx >> 6, d = idx & 63;
        buf[l][d] = Vb[(long)(b * 128 + l) * 1024 + h * 64 + d];
    }
    __syncthreads();
    {
        const int p = tid;
        float acc[64];
#pragma unroll
        for (int d = 0; d < 64; d++) acc[d] = 0.f;
        const float* vr = vpm + (long)p * 4096;
        for (int l = 0; l <= p; l++) {
            float cf = vr[l];
#pragma unroll
            for (int d = 0; d < 64; d++) acc[d] += cf * buf[l][d];
        }
        long base = (long)bh * 8192 + (long)(p >> 6) * 4096 + (p & 63);
#pragma unroll
        for (int d = 0; d < 64; d++) {
            float v = acc[d];
            __nv_bfloat16 hv = __float2bfloat16(v);
            VTh[base + d * 64] = hv;
            VTl[base + d * 64] = __float2bfloat16(v - __bfloat162float(hv));
        }
    }
}

// ---------------- HMMA flash attention ----------------
#define AT_QH 0
#define AT_QL 16384
#define AT_KH 32768
#define AT_KL 49152
#define AT_VH 65536
#define AT_VL 81920
#define AT_SMEM 98304

__global__ __launch_bounds__(256)
void attn_hmma(const float* __restrict__ Q,
               const __nv_bfloat16* __restrict__ KPh, const __nv_bfloat16* __restrict__ KPl,
               const __nv_bfloat16* __restrict__ VTh, const __nv_bfloat16* __restrict__ VTl,
               const float* __restrict__ fcos, const float* __restrict__ fsin,
               __nv_bfloat16* __restrict__ Oh, __nv_bfloat16* __restrict__ Ol)
{
    extern __shared__ __align__(128) char sm[];
    const uint32_t sb = smem_u32(sm);
    const int tid = threadIdx.x, lane = tid & 31, w = tid >> 5;
    const int bh = blockIdx.y;
    const int b = bh >> 4, h = bh & 15;
    const int lt = blockIdx.x;
    const int lbase = lt * 128;

    // cp.async KP hi/lo + VPT hi/lo into swizzled smem (128 rows of 128B each)
    for (int i = tid; i < 1024; i += 256) {
        int row = i >> 3, c = i & 7;
        uint32_t off = (uint32_t)row * 128 + (((uint32_t)(c ^ (row & 7))) << 4);
        long src = (long)bh * 8192 + (long)row * 64 + c * 8;
        cp16(sb + AT_KH + off, KPh + src);
        cp16(sb + AT_KL + off, KPl + src);
        cp16(sb + AT_VH + off, VTh + src);
        cp16(sb + AT_VL + off, VTl + src);
    }
    asm volatile("cp.async.commit_group;" ::: "memory");

    // Q: load fp32, RoPE, hi/lo split, store swizzled bf16
    {
        const float* Qg = Q + ((long)(b * 4096 + lbase)) * 1024 + h * 64;
#pragma unroll
        for (int it = 0; it < 16; it++) {
            int idx = it * 256 + tid;
            int row = idx >> 5, i = idx & 31;
            float2 q = *(const float2*)(Qg + (long)row * 1024 + 2 * i);
            int l = lbase + row;
            float c = fcos[l * 32 + i], s = fsin[l * 32 + i];
            float xr = q.x * c - q.y * s;
            float xi = q.x * s + q.y * c;
            uint32_t off = (uint32_t)row * 128
                         + (((uint32_t)((i >> 2) ^ (row & 7))) << 4) + (i & 3) * 4;
            *(uint32_t*)(sm + AT_QH + off) = pack_hi(xr, xi);
            *(uint32_t*)(sm + AT_QL + off) = pack_lo(xr, xi);
        }
    }
    asm volatile("cp.async.wait_group 0;" ::: "memory");
    __syncthreads();

    const int arow = w * 16 + (lane & 15);
    const int ac   = lane >> 4;
    const int brow = ((lane >> 4) << 3) + (lane & 7);
    const int bsel = (lane >> 3) & 1;

    // ---- S = Q @ KP^T : 16 n-tiles, K=64 ----
    float accS[16][4];
#pragma unroll
    for (int nt = 0; nt < 16; nt++)
#pragma unroll
        for (int e = 0; e < 4; e++) accS[nt][e] = 0.f;

#pragma unroll
    for (int ks = 0; ks < 4; ks++) {
        uint32_t aHi[4], aLo[4];
        uint32_t aoff = (uint32_t)arow * 128 + ((uint32_t)((ks * 2 + ac) ^ (arow & 7)) << 4);
        ldsm_x4(aHi, sb + AT_QH + aoff);
        ldsm_x4(aLo, sb + AT_QL + aoff);
#pragma unroll
        for (int nt2 = 0; nt2 < 8; nt2++) {
            int r = nt2 * 16 + brow;
            uint32_t boff = (uint32_t)r * 128 + ((uint32_t)((ks * 2 + bsel) ^ (r & 7)) << 4);
            uint32_t bH[4], bL[4];
            ldsm_x4(bH, sb + AT_KH + boff);
            ldsm_x4(bL, sb + AT_KL + boff);
            mma_bf16(accS[2 * nt2],     aHi, bH);
            mma_bf16(accS[2 * nt2 + 1], aHi, bH + 2);
            mma_bf16(accS[2 * nt2],     aLo, bH);
            mma_bf16(accS[2 * nt2 + 1], aLo, bH + 2);
            mma_bf16(accS[2 * nt2],     aHi, bL);
            mma_bf16(accS[2 * nt2 + 1], aHi, bL + 2);
        }
    }

    // ---- scale + causal mask (first l-tile only) ----
#pragma unroll
    for (int nt = 0; nt < 16; nt++)
#pragma unroll
        for (int e = 0; e < 4; e++) accS[nt][e] *= 0.125f;
    if (lt == 0) {
        int r0 = w * 16 + (lane >> 2);
#pragma unroll
        for (int nt = 0; nt < 16; nt++)
#pragma unroll
            for (int e = 0; e < 4; e++) {
                int col = nt * 8 + (lane & 3) * 2 + (e & 1);
                int r = r0 + 8 * (e >> 1);
                if (col > r) accS[nt][e] = -1e30f;
            }
    }

    // ---- fragment softmax (rows r0 and r0+8; reduce across quad lanes) ----
    {
        float mx0 = -1e30f, mx1 = -1e30f;
#pragma unroll
        for (int nt = 0; nt < 16; nt++) {
            mx0 = fmaxf(mx0, fmaxf(accS[nt][0], accS[nt][1]));
            mx1 = fmaxf(mx1, fmaxf(accS[nt][2], accS[nt][3]));
        }
        mx0 = fmaxf(mx0, __shfl_xor_sync(0xFFFFFFFFu, mx0, 1));
        mx0 = fmaxf(mx0, __shfl_xor_sync(0xFFFFFFFFu, mx0, 2));
        mx1 = fmaxf(mx1, __shfl_xor_sync(0xFFFFFFFFu, mx1, 1));
        mx1 = fmaxf(mx1, __shfl_xor_sync(0xFFFFFFFFu, mx1, 2));
        float s0 = 0.f, s1 = 0.f;
#pragma unroll
        for (int nt = 0; nt < 16; nt++) {
            accS[nt][0] = __expf(accS[nt][0] - mx0); s0 += accS[nt][0];
            accS[nt][1] = __expf(accS[nt][1] - mx0); s0 += accS[nt][1];
            accS[nt][2] = __expf(accS[nt][2] - mx1); s1 += accS[nt][2];
            accS[nt][3] = __expf(accS[nt][3] - mx1); s1 += accS[nt][3];
        }
        s0 += __shfl_xor_sync(0xFFFFFFFFu, s0, 1);
        s0 += __shfl_xor_sync(0xFFFFFFFFu, s0, 2);
        s1 += __shfl_xor_sync(0xFFFFFFFFu, s1, 1);
        s1 += __shfl_xor_sync(0xFFFFFFFFu, s1, 2);
        float i0 = 1.f / s0, i1 = 1.f / s1;
#pragma unroll
        for (int nt = 0; nt < 16; nt++) {
            accS[nt][0] *= i0; accS[nt][1] *= i0;
            accS[nt][2] *= i1; accS[nt][3] *= i1;
        }
    }

    // ---- repack W into A-operand fragments (hi/lo) for each p-kstep ----
    uint32_t wH[8][4], wL[8][4];
#pragma unroll
    for (int kp = 0; kp < 8; kp++) {
        wH[kp][0] = pack_hi(accS[2 * kp][0],     accS[2 * kp][1]);
        wH[kp][1] = pack_hi(accS[2 * kp][2],     accS[2 * kp][3]);
        wH[kp][2] = pack_hi(accS[2 * kp + 1][0], accS[2 * kp + 1][1]);
        wH[kp][3] = pack_hi(accS[2 * kp + 1][2], accS[2 * kp + 1][3]);
        wL[kp][0] = pack_lo(accS[2 * kp][0],     accS[2 * kp][1]);
        wL[kp][1] = pack_lo(accS[2 * kp][2],     accS[2 * kp][3]);
        wL[kp][2] = pack_lo(accS[2 * kp + 1][0], accS[2 * kp + 1][1]);
        wL[kp][3] = pack_lo(accS[2 * kp + 1][2], accS[2 * kp + 1][3]);
    }

    // ---- O = W @ VP : 8 d-tiles, K=128 (8 ksteps over p) ----
    float accO[8][4];
#pragma unroll
    for (int nt = 0; nt < 8; nt++)
#pragma unroll
        for (int e = 0; e < 4; e++) accO[nt][e] = 0.f;

#pragma unroll
    for (int kp = 0; kp < 8; kp++) {
        uint32_t vbase = (uint32_t)(kp >> 2) * 8192;
        int kl = kp & 3;
#pragma unroll
        for (int nt2 = 0; nt2 < 4; nt2++) {
            int r = nt2 * 16 + brow;
            uint32_t boff = vbase + (uint32_t)r * 128
                          + ((uint32_t)((kl * 2 + bsel) ^ (r & 7)) << 4);
            uint32_t bH[4], bL[4];
            ldsm_x4(bH, sb + AT_VH + boff);
            ldsm_x4(bL, sb + AT_VL + boff);
            mma_bf16(accO[2 * nt2],     wH[kp], bH);
            mma_bf16(accO[2 * nt2 + 1], wH[kp], bH + 2);
            mma_bf16(accO[2 * nt2],     wL[kp], bH);
            mma_bf16(accO[2 * nt2 + 1], wL[kp], bH + 2);
            mma_bf16(accO[2 * nt2],     wH[kp], bL);
            mma_bf16(accO[2 * nt2 + 1], wH[kp], bL + 2);
        }
    }

    // ---- epilogue: write O as bf16 hi/lo into the final GEMM's A buffers ----
    {
        long row0 = (long)(b * 4096 + lbase + w * 16 + (lane >> 2));
        int col = h * 64 + (lane & 3) * 2;
#pragma unroll
        for (int nt = 0; nt < 8; nt++) {
            long o0 = row0 * 1024 + col + nt * 8;
            long o1 = (row0 + 8) * 1024 + col + nt * 8;
            *(uint32_t*)(Oh + o0) = pack_hi(accO[nt][0], accO[nt][1]);
            *(uint32_t*)(Ol + o0) = pack_lo(accO[nt][0], accO[nt][1]);
            *(uint32_t*)(Oh + o1) = pack_hi(accO[nt][2], accO[nt][3]);
            *(uint32_t*)(Ol + o1) = pack_lo(accO[nt][2], accO[nt][3]);
        }
    }
}

// ---------------- launch ----------------
extern "C" void kernel_launch(void* const* d_in, const int* in_sizes, int n_in,
                              void* d_out, int out_size)
{
    const float* x    = (const float*)d_in[0];
    const float* fcos = (const float*)d_in[1];
    const float* fsin = (const float*)d_in[2];
    const float* Wq   = (const float*)d_in[3];
    const float* Wk   = (const float*)d_in[4];
    const float* Wv   = (const float*)d_in[5];
    const float* Wo   = (const float*)d_in[6];
    const float* kpm  = (const float*)d_in[7];
    const float* vpm  = (const float*)d_in[8];
    float* out = (float*)d_out;

    float *pQ, *pK, *pV;
    cudaGetSymbolAddress((void**)&pQ, g_Q);
    cudaGetSymbolAddress((void**)&pK, g_K);
    cudaGetSymbolAddress((void**)&pV, g_V);
    __nv_bfloat16 *pAh, *pAl, *pWqh, *pWql, *pWoh, *pWol, *pKPh, *pKPl, *pVTh, *pVTl;
    cudaGetSymbolAddress((void**)&pAh,  g_Ah);
    cudaGetSymbolAddress((void**)&pAl,  g_Al);
    cudaGetSymbolAddress((void**)&pWqh, g_Wqh);
    cudaGetSymbolAddress((void**)&pWql, g_Wql);
    cudaGetSymbolAddress((void**)&pWoh, g_Woh);
    cudaGetSymbolAddress((void**)&pWol, g_Wol);
    cudaGetSymbolAddress((void**)&pKPh, g_KPh);
    cudaGetSymbolAddress((void**)&pKPl, g_KPl);
    cudaGetSymbolAddress((void**)&pVTh, g_VTh);
    cudaGetSymbolAddress((void**)&pVTl, g_VTl);

    cudaFuncSetAttribute(hmma_gemm2, cudaFuncAttributeMaxDynamicSharedMemorySize, HG2_SMEM);
    cudaFuncSetAttribute(attn_hmma, cudaFuncAttributeMaxDynamicSharedMemorySize, AT_SMEM);

    // hi/lo splits of x, Wq, Wo
    cvt_hilo<<<16384, 256>>>(x, pAh, pAl);
    cvt_hilo<<<1024, 256>>>(Wq, pWqh, pWql);
    cvt_hilo<<<1024, 256>>>(Wo, pWoh, pWol);

    // Q = x @ Wq^T via pipelined HMMA
    {
        dim3 grid(8, 128, 1);
        hmma_gemm2<<<grid, 256, HG2_SMEM>>>(pAh, pAl, pWqh, pWql, pQ);
    }
    // K,V for first 128 rows of each batch (small, fp32 SGEMM)
    {
        dim3 grid(8, 4, 2);
        sgemm_tn<<<grid, 256>>>(x, Wk, pK, Wv, pV, 4194304L);
    }
    // K_proj / V_proj (RoPE on K inside), emitted as bf16 hi/lo
    proj_kernel<<<64, 128>>>(pK, pV, kpm, vpm, fcos, fsin, pKPh, pKPl, pVTh, pVTl);
    // HMMA flash attention -> writes O hi/lo straight into g_Ah/g_Al
    {
        dim3 grid(32, 64, 1);
        attn_hmma<<<grid, 256, AT_SMEM>>>(pQ, pKPh, pKPl, pVTh, pVTl, fcos, fsin, pAh, pAl);
    }
    // out = O @ Wo^T via pipelined HMMA
    {
        dim3 grid(8, 128, 1);
        hmma_gemm2<<<grid, 256, HG2_SMEM>>>(pAh, pAl, pWoh, pWol, out);
    }
}

// round 11
// speedup vs baseline: 1.0005x; 1.0005x over previous
#include <cuda_runtime.h>
#include <cuda_bf16.h>
#include <cstdint>

// Problem constants: B=4, L=4096, D=1024, H=16, HD=64, P=128, MAXLEN=4096

// ---------------- scratch (no cudaMalloc allowed) ----------------
__device__ float g_Q[16384L * 1024];   // Q = x@Wq^T (pre-RoPE)
__device__ float g_K[512L * 1024];     // K for l<128 per batch
__device__ float g_V[512L * 1024];     // V for l<128 per batch
// bf16 hi/lo splits (A reused for x then attention output O)
__device__ __align__(16) __nv_bfloat16 g_Ah[16384L * 1024];
__device__ __align__(16) __nv_bfloat16 g_Al[16384L * 1024];
__device__ __align__(16) __nv_bfloat16 g_Wqh[1024 * 1024];
__device__ __align__(16) __nv_bfloat16 g_Wql[1024 * 1024];
__device__ __align__(16) __nv_bfloat16 g_Woh[1024 * 1024];
__device__ __align__(16) __nv_bfloat16 g_Wol[1024 * 1024];
// projections, pre-split (proj_kernel outputs)
__device__ __align__(16) __nv_bfloat16 g_KPh[64L * 128 * 64]; // [bh][p][d]
__device__ __align__(16) __nv_bfloat16 g_KPl[64L * 128 * 64];
__device__ __align__(16) __nv_bfloat16 g_VTh[64L * 2 * 64 * 64]; // [bh][half][d][p&63]
__device__ __align__(16) __nv_bfloat16 g_VTl[64L * 2 * 64 * 64];

__device__ __forceinline__ uint32_t smem_u32(const void* p) {
    uint32_t a;
    asm("{ .reg .u64 t; cvta.to.shared.u64 t, %1; cvt.u32.u64 %0, t; }" : "=r"(a) : "l"(p));
    return a;
}
__device__ __forceinline__ void ldsm_x4(uint32_t* r, uint32_t addr) {
    asm volatile("ldmatrix.sync.aligned.m8n8.x4.shared.b16 {%0,%1,%2,%3}, [%4];"
                 : "=r"(r[0]), "=r"(r[1]), "=r"(r[2]), "=r"(r[3]) : "r"(addr));
}
__device__ __forceinline__ void mma_bf16(float* c, const uint32_t* a, const uint32_t* b) {
    asm volatile("mma.sync.aligned.m16n8k16.row.col.f32.bf16.bf16.f32 "
                 "{%0,%1,%2,%3}, {%4,%5,%6,%7}, {%8,%9}, {%0,%1,%2,%3};"
                 : "+f"(c[0]), "+f"(c[1]), "+f"(c[2]), "+f"(c[3])
                 : "r"(a[0]), "r"(a[1]), "r"(a[2]), "r"(a[3]), "r"(b[0]), "r"(b[1]));
}
__device__ __forceinline__ void cp16(uint32_t dst, const void* src) {
    asm volatile("cp.async.cg.shared.global [%0], [%1], 16;" :: "r"(dst), "l"(src) : "memory");
}
__device__ __forceinline__ uint32_t pack_hi(float a, float b) {
    return (uint32_t)__bfloat16_as_ushort(__float2bfloat16(a))
         | ((uint32_t)__bfloat16_as_ushort(__float2bfloat16(b)) << 16);
}
__device__ __forceinline__ uint32_t pack_lo(float a, float b) {
    float ra = a - __bfloat162float(__float2bfloat16(a));
    float rb = b - __bfloat162float(__float2bfloat16(b));
    return (uint32_t)__bfloat16_as_ushort(__float2bfloat16(ra))
         | ((uint32_t)__bfloat16_as_ushort(__float2bfloat16(rb)) << 16);
}

// ---------------- fp32 -> bf16 hi/lo split (elementwise) ----------------
__global__ __launch_bounds__(256)
void cvt_hilo(const float* __restrict__ A, __nv_bfloat16* __restrict__ H,
              __nv_bfloat16* __restrict__ L)
{
    long i = (long)blockIdx.x * 256 + threadIdx.x;
    float4 v = ((const float4*)A)[i];
    uint2 hp = make_uint2(pack_hi(v.x, v.y), pack_hi(v.z, v.w));
    uint2 lp = make_uint2(pack_lo(v.x, v.y), pack_lo(v.z, v.w));
    ((uint2*)H)[i] = hp;
    ((uint2*)L)[i] = lp;
}

// ============ pipelined HMMA GEMM (validated round 7) ============
#define HG2_STAGE 65536
#define HG2_SMEM  131072

__device__ __forceinline__ void hg2_load(uint32_t sbase, int tid,
    const __nv_bfloat16* b0, const __nv_bfloat16* b1,
    const __nv_bfloat16* b2, const __nv_bfloat16* b3, int kc)
{
#pragma unroll
    for (int arr = 0; arr < 4; arr++) {
        const __nv_bfloat16* bp = (arr == 0) ? b0 : (arr == 1) ? b1 : (arr == 2) ? b2 : b3;
        uint32_t aoff = sbase + arr * 16384;
#pragma unroll
        for (int q = 0; q < 4; q++) {
            int idx = q * 256 + tid;
            int row = idx >> 3, c = idx & 7;
            uint32_t dst = aoff + row * 128 + (((uint32_t)(c ^ (row & 7))) << 4);
            cp16(dst, bp + (long)row * 1024 + kc * 64 + c * 8);
        }
    }
    asm volatile("cp.async.commit_group;" ::: "memory");
}

__global__ __launch_bounds__(256)
void hmma_gemm2(const __nv_bfloat16* __restrict__ Ah, const __nv_bfloat16* __restrict__ Al,
                const __nv_bfloat16* __restrict__ Bh, const __nv_bfloat16* __restrict__ Bl,
                float* __restrict__ C)
{
    extern __shared__ __align__(128) char sm[];
    const uint32_t sb = smem_u32(sm);
    const int tid = threadIdx.x, lane = tid & 31, wid = tid >> 5;
    const int wm = wid & 3, wn = wid >> 2;
    const long tile_m = (long)blockIdx.y * 128;
    const long tile_n = (long)blockIdx.x * 128;

    const __nv_bfloat16* base0 = Ah + tile_m * 1024;
    const __nv_bfloat16* base1 = Al + tile_m * 1024;
    const __nv_bfloat16* base2 = Bh + tile_n * 1024;
    const __nv_bfloat16* base3 = Bl + tile_n * 1024;

    float acc[2][8][4];
#pragma unroll
    for (int mt = 0; mt < 2; mt++)
#pragma unroll
        for (int nt = 0; nt < 8; nt++)
#pragma unroll
            for (int e = 0; e < 4; e++) acc[mt][nt][e] = 0.f;

    const int arow = wm * 32 + (lane & 15);
    const int ac   = lane >> 4;
    const int brow = wn * 64 + ((lane >> 4) << 3) + (lane & 7);
    const int bc   = (lane >> 3) & 1;

    hg2_load(sb, tid, base0, base1, base2, base3, 0);

    for (int kc = 0; kc < 16; kc++) {
        if (kc < 15) {
            hg2_load(sb + ((kc + 1) & 1) * HG2_STAGE, tid, base0, base1, base2, base3, kc + 1);
            asm volatile("cp.async.wait_group 1;" ::: "memory");
        } else {
            asm volatile("cp.async.wait_group 0;" ::: "memory");
        }
        __syncthreads();

        const uint32_t sbase = sb + (kc & 1) * HG2_STAGE;
#pragma unroll
        for (int ks = 0; ks < 4; ks++) {
            uint32_t aHi[2][4], aLo[2][4], bf[8][2];
            const int cA = ks * 2 + ac;
#pragma unroll
            for (int mt = 0; mt < 2; mt++) {
                int r = arow + mt * 16;
                uint32_t ad = sbase + r * 128 + ((uint32_t)(cA ^ (r & 7)) << 4);
                ldsm_x4(aHi[mt], ad);
                ldsm_x4(aLo[mt], ad + 16384);
            }
            const int cB = ks * 2 + bc;
#pragma unroll
            for (int nt2 = 0; nt2 < 4; nt2++) {
                int r = brow + nt2 * 16;
                uint32_t bd = sbase + 32768 + r * 128 + ((uint32_t)(cB ^ (r & 7)) << 4);
                uint32_t t[4]; ldsm_x4(t, bd);
                bf[nt2 * 2][0] = t[0]; bf[nt2 * 2][1] = t[1];
                bf[nt2 * 2 + 1][0] = t[2]; bf[nt2 * 2 + 1][1] = t[3];
            }
#pragma unroll
            for (int mt = 0; mt < 2; mt++)
#pragma unroll
                for (int nt = 0; nt < 8; nt++)
                    mma_bf16(acc[mt][nt], aHi[mt], bf[nt]);
#pragma unroll
            for (int mt = 0; mt < 2; mt++)
#pragma unroll
                for (int nt = 0; nt < 8; nt++)
                    mma_bf16(acc[mt][nt], aLo[mt], bf[nt]);
#pragma unroll
            for (int nt2 = 0; nt2 < 4; nt2++) {
                int r = brow + nt2 * 16;
                uint32_t bd = sbase + 49152 + r * 128 + ((uint32_t)(cB ^ (r & 7)) << 4);
                uint32_t t[4]; ldsm_x4(t, bd);
                bf[nt2 * 2][0] = t[0]; bf[nt2 * 2][1] = t[1];
                bf[nt2 * 2 + 1][0] = t[2]; bf[nt2 * 2 + 1][1] = t[3];
            }
#pragma unroll
            for (int mt = 0; mt < 2; mt++)
#pragma unroll
                for (int nt = 0; nt < 8; nt++)
                    mma_bf16(acc[mt][nt], aHi[mt], bf[nt]);
        }
        __syncthreads();
    }

#pragma unroll
    for (int mt = 0; mt < 2; mt++) {
#pragma unroll
        for (int nt = 0; nt < 8; nt++) {
            long row0 = tile_m + wm * 32 + mt * 16 + (lane >> 2);
            long col  = tile_n + wn * 64 + nt * 8 + (lane & 3) * 2;
            *(float2*)(C + row0 * 1024 + col)       = make_float2(acc[mt][nt][0], acc[mt][nt][1]);
            *(float2*)(C + (row0 + 8) * 1024 + col) = make_float2(acc[mt][nt][2], acc[mt][nt][3]);
        }
    }
}

// ---------------- small SGEMM for K/V (first 128 rows per batch) ----------------
__global__ __launch_bounds__(256, 2)
void sgemm_tn(const float* __restrict__ A, const float* __restrict__ B,
              float* __restrict__ C,
              const float* __restrict__ B2, float* __restrict__ C2,
              long aGroupStride)
{
    if (blockIdx.z == 1) { B = B2; C = C2; }

    __shared__ float As[16][128];
    __shared__ float Bs[16][128];

    const int tid = threadIdx.x;
    const int tx = tid & 15;
    const int ty = tid >> 4;
    const long aTile = (long)blockIdx.y * aGroupStride;
    const long bTile = (long)blockIdx.x * 128 * 1024;

    float acc[8][8];
#pragma unroll
    for (int i = 0; i < 8; i++)
#pragma unroll
        for (int j = 0; j < 8; j++) acc[i][j] = 0.f;

    for (int k0 = 0; k0 < 1024; k0 += 16) {
#pragma unroll
        for (int t = 0; t < 2; t++) {
            int f = tid + t * 256;
            int row = f >> 2;
            int c4  = f & 3;
            float4 va = *(const float4*)(A + aTile + (long)row * 1024 + k0 + c4 * 4);
            As[c4 * 4 + 0][row] = va.x;
            As[c4 * 4 + 1][row] = va.y;
            As[c4 * 4 + 2][row] = va.z;
            As[c4 * 4 + 3][row] = va.w;
            float4 vb = *(const float4*)(B + bTile + (long)row * 1024 + k0 + c4 * 4);
            Bs[c4 * 4 + 0][row] = vb.x;
            Bs[c4 * 4 + 1][row] = vb.y;
            Bs[c4 * 4 + 2][row] = vb.z;
            Bs[c4 * 4 + 3][row] = vb.w;
        }
        __syncthreads();
#pragma unroll
        for (int kk = 0; kk < 16; kk++) {
            float a[8], b[8];
            *(float4*)&a[0] = *(const float4*)&As[kk][ty * 8];
            *(float4*)&a[4] = *(const float4*)&As[kk][ty * 8 + 4];
            *(float4*)&b[0] = *(const float4*)&Bs[kk][tx * 8];
            *(float4*)&b[4] = *(const float4*)&Bs[kk][tx * 8 + 4];
#pragma unroll
            for (int i = 0; i < 8; i++)
#pragma unroll
                for (int j = 0; j < 8; j++)
                    acc[i][j] += a[i] * b[j];
        }
        __syncthreads();
    }

#pragma unroll
    for (int i = 0; i < 8; i++) {
        long crow = (long)blockIdx.y * 128 + ty * 8 + i;
        long cbase = crow * 1024 + blockIdx.x * 128 + tx * 8;
        *(float4*)(C + cbase)     = make_float4(acc[i][0], acc[i][1], acc[i][2], acc[i][3]);
        *(float4*)(C + cbase + 4) = make_float4(acc[i][4], acc[i][5], acc[i][6], acc[i][7]);
    }
}

// ---------------- projection kernel: KP/VP in bf16 hi/lo ----------------
__global__ __launch_bounds__(128)
void proj_kernel(const float* __restrict__ Kb, const float* __restrict__ Vb,
                 const float* __restrict__ kpm, const float* __restrict__ vpm,
                 const float* __restrict__ fcos, const float* __restrict__ fsin,
                 __nv_bfloat16* __restrict__ KPh, __nv_bfloat16* __restrict__ KPl,
                 __nv_bfloat16* __restrict__ VTh, __nv_bfloat16* __restrict__ VTl)
{
    __shared__ float buf[128][64];
    const int bh = blockIdx.x;
    const int b = bh >> 4, h = bh & 15;
    const int tid = threadIdx.x;

    // ---- K pass (with RoPE) ----
    for (int idx = tid; idx < 128 * 64; idx += 128) {
        int l = idx >> 6, d = idx & 63;
        buf[l][d] = Kb[(long)(b * 128 + l) * 1024 + h * 64 + d];
    }
    __syncthreads();
    for (int idx = tid; idx < 128 * 32; idx += 128) {
        int l = idx >> 5, i = idx & 31;
        float c = fcos[l * 32 + i], s = fsin[l * 32 + i];
        float tr = buf[l][2 * i], ti = buf[l][2 * i + 1];
        buf[l][2 * i]     = tr * c - ti * s;
        buf[l][2 * i + 1] = tr * s + ti * c;
    }
    __syncthreads();
    {
        const int p = tid;
        float acc[64];
#pragma unroll
        for (int d = 0; d < 64; d++) acc[d] = 0.f;
        const float* kr = kpm + (long)p * 4096;
        for (int l = 0; l <= p; l++) {
            float cf = kr[l];
#pragma unroll
            for (int d = 0; d < 64; d++) acc[d] += cf * buf[l][d];
        }
        long dst = (long)bh * 8192 + (long)p * 64;
#pragma unroll
        for (int d = 0; d < 64; d += 2) {
            *(uint32_t*)(KPh + dst + d) = pack_hi(acc[d], acc[d + 1]);
            *(uint32_t*)(KPl + dst + d) = pack_lo(acc[d], acc[d + 1]);
        }
    }
    __syncthreads();

    // ---- V pass (no RoPE), transposed output ----
    for (int idx = tid; idx < 128 * 64; idx += 128) {
        int l = idx >> 6, d = idx & 63;
        buf[l][d] = Vb[(long)(b * 128 + l) * 1024 + h * 64 + d];
    }
    __syncthreads();
    {
        const int p = tid;
        float acc[64];
#pragma unroll
        for (int d = 0; d < 64; d++) acc[d] = 0.f;
        const float* vr = vpm + (long)p * 4096;
        for (int l = 0; l <= p; l++) {
            float cf = vr[l];
#pragma unroll
            for (int d = 0; d < 64; d++) acc[d] += cf * buf[l][d];
        }
        long base = (long)bh * 8192 + (long)(p >> 6) * 4096 + (p & 63);
#pragma unroll
        for (int d = 0; d < 64; d++) {
            float v = acc[d];
            __nv_bfloat16 hv = __float2bfloat16(v);
            VTh[base + d * 64] = hv;
            VTl[base + d * 64] = __float2bfloat16(v - __bfloat162float(hv));
        }
    }
}

// ---------------- HMMA flash attention ----------------
#define AT_QH 0
#define AT_QL 16384
#define AT_KH 32768
#define AT_KL 49152
#define AT_VH 65536
#define AT_VL 81920
#define AT_SMEM 98304

__global__ __launch_bounds__(256)
void attn_hmma(const float* __restrict__ Q,
               const __nv_bfloat16* __restrict__ KPh, const __nv_bfloat16* __restrict__ KPl,
               const __nv_bfloat16* __restrict__ VTh, const __nv_bfloat16* __restrict__ VTl,
               const float* __restrict__ fcos, const float* __restrict__ fsin,
               __nv_bfloat16* __restrict__ Oh, __nv_bfloat16* __restrict__ Ol)
{
    extern __shared__ __align__(128) char sm[];
    const uint32_t sb = smem_u32(sm);
    const int tid = threadIdx.x, lane = tid & 31, w = tid >> 5;
    const int bh = blockIdx.y;
    const int b = bh >> 4, h = bh & 15;
    const int lt = blockIdx.x;
    const int lbase = lt * 128;

    // cp.async KP hi/lo + VPT hi/lo into swizzled smem (128 rows of 128B each)
    for (int i = tid; i < 1024; i += 256) {
        int row = i >> 3, c = i & 7;
        uint32_t off = (uint32_t)row * 128 + (((uint32_t)(c ^ (row & 7))) << 4);
        long src = (long)bh * 8192 + (long)row * 64 + c * 8;
        cp16(sb + AT_KH + off, KPh + src);
        cp16(sb + AT_KL + off, KPl + src);
        cp16(sb + AT_VH + off, VTh + src);
        cp16(sb + AT_VL + off, VTl + src);
    }
    asm volatile("cp.async.commit_group;" ::: "memory");

    // Q: load fp32, RoPE, hi/lo split, store swizzled bf16
    {
        const float* Qg = Q + ((long)(b * 4096 + lbase)) * 1024 + h * 64;
#pragma unroll
        for (int it = 0; it < 16; it++) {
            int idx = it * 256 + tid;
            int row = idx >> 5, i = idx & 31;
            float2 q = *(const float2*)(Qg + (long)row * 1024 + 2 * i);
            int l = lbase + row;
            float c = fcos[l * 32 + i], s = fsin[l * 32 + i];
            float xr = q.x * c - q.y * s;
            float xi = q.x * s + q.y * c;
            uint32_t off = (uint32_t)row * 128
                         + (((uint32_t)((i >> 2) ^ (row & 7))) << 4) + (i & 3) * 4;
            *(uint32_t*)(sm + AT_QH + off) = pack_hi(xr, xi);
            *(uint32_t*)(sm + AT_QL + off) = pack_lo(xr, xi);
        }
    }
    asm volatile("cp.async.wait_group 0;" ::: "memory");
    __syncthreads();

    const int arow = w * 16 + (lane & 15);
    const int ac   = lane >> 4;
    const int brow = ((lane >> 4) << 3) + (lane & 7);
    const int bsel = (lane >> 3) & 1;

    // ---- S = Q @ KP^T : 16 n-tiles, K=64 ----
    float accS[16][4];
#pragma unroll
    for (int nt = 0; nt < 16; nt++)
#pragma unroll
        for (int e = 0; e < 4; e++) accS[nt][e] = 0.f;

#pragma unroll
    for (int ks = 0; ks < 4; ks++) {
        uint32_t aHi[4], aLo[4];
        uint32_t aoff = (uint32_t)arow * 128 + ((uint32_t)((ks * 2 + ac) ^ (arow & 7)) << 4);
        ldsm_x4(aHi, sb + AT_QH + aoff);
        ldsm_x4(aLo, sb + AT_QL + aoff);
#pragma unroll
        for (int nt2 = 0; nt2 < 8; nt2++) {
            int r = nt2 * 16 + brow;
            uint32_t boff = (uint32_t)r * 128 + ((uint32_t)((ks * 2 + bsel) ^ (r & 7)) << 4);
            uint32_t bH[4], bL[4];
            ldsm_x4(bH, sb + AT_KH + boff);
            ldsm_x4(bL, sb + AT_KL + boff);
            mma_bf16(accS[2 * nt2],     aHi, bH);
            mma_bf16(accS[2 * nt2 + 1], aHi, bH + 2);
            mma_bf16(accS[2 * nt2],     aLo, bH);
            mma_bf16(accS[2 * nt2 + 1], aLo, bH + 2);
            mma_bf16(accS[2 * nt2],     aHi, bL);
            mma_bf16(accS[2 * nt2 + 1], aHi, bL + 2);
        }
    }

    // ---- scale + causal mask (first l-tile only) ----
#pragma unroll
    for (int nt = 0; nt < 16; nt++)
#pragma unroll
        for (int e = 0; e < 4; e++) accS[nt][e] *= 0.125f;
    if (lt == 0) {
        int r0 = w * 16 + (lane >> 2);
#pragma unroll
        for (int nt = 0; nt < 16; nt++)
#pragma unroll
            for (int e = 0; e < 4; e++) {
                int col = nt * 8 + (lane & 3) * 2 + (e & 1);
                int r = r0 + 8 * (e >> 1);
                if (col > r) accS[nt][e] = -1e30f;
            }
    }

    // ---- fragment softmax (rows r0 and r0+8; reduce across quad lanes) ----
    {
        float mx0 = -1e30f, mx1 = -1e30f;
#pragma unroll
        for (int nt = 0; nt < 16; nt++) {
            mx0 = fmaxf(mx0, fmaxf(accS[nt][0], accS[nt][1]));
            mx1 = fmaxf(mx1, fmaxf(accS[nt][2], accS[nt][3]));
        }
        mx0 = fmaxf(mx0, __shfl_xor_sync(0xFFFFFFFFu, mx0, 1));
        mx0 = fmaxf(mx0, __shfl_xor_sync(0xFFFFFFFFu, mx0, 2));
        mx1 = fmaxf(mx1, __shfl_xor_sync(0xFFFFFFFFu, mx1, 1));
        mx1 = fmaxf(mx1, __shfl_xor_sync(0xFFFFFFFFu, mx1, 2));
        float s0 = 0.f, s1 = 0.f;
#pragma unroll
        for (int nt = 0; nt < 16; nt++) {
            accS[nt][0] = __expf(accS[nt][0] - mx0); s0 += accS[nt][0];
            accS[nt][1] = __expf(accS[nt][1] - mx0); s0 += accS[nt][1];
            accS[nt][2] = __expf(accS[nt][2] - mx1); s1 += accS[nt][2];
            accS[nt][3] = __expf(accS[nt][3] - mx1); s1 += accS[nt][3];
        }
        s0 += __shfl_xor_sync(0xFFFFFFFFu, s0, 1);
        s0 += __shfl_xor_sync(0xFFFFFFFFu, s0, 2);
        s1 += __shfl_xor_sync(0xFFFFFFFFu, s1, 1);
        s1 += __shfl_xor_sync(0xFFFFFFFFu, s1, 2);
        float i0 = 1.f / s0, i1 = 1.f / s1;
#pragma unroll
        for (int nt = 0; nt < 16; nt++) {
            accS[nt][0] *= i0; accS[nt][1] *= i0;
            accS[nt][2] *= i1; accS[nt][3] *= i1;
        }
    }

    // ---- repack W into A-operand fragments (hi/lo) for each p-kstep ----
    uint32_t wH[8][4], wL[8][4];
#pragma unroll
    for (int kp = 0; kp < 8; kp++) {
        wH[kp][0] = pack_hi(accS[2 * kp][0],     accS[2 * kp][1]);
        wH[kp][1] = pack_hi(accS[2 * kp][2],     accS[2 * kp][3]);
        wH[kp][2] = pack_hi(accS[2 * kp + 1][0], accS[2 * kp + 1][1]);
        wH[kp][3] = pack_hi(accS[2 * kp + 1][2], accS[2 * kp + 1][3]);
        wL[kp][0] = pack_lo(accS[2 * kp][0],     accS[2 * kp][1]);
        wL[kp][1] = pack_lo(accS[2 * kp][2],     accS[2 * kp][3]);
        wL[kp][2] = pack_lo(accS[2 * kp + 1][0], accS[2 * kp + 1][1]);
        wL[kp][3] = pack_lo(accS[2 * kp + 1][2], accS[2 * kp + 1][3]);
    }

    // ---- O = W @ VP : 8 d-tiles, K=128 (8 ksteps over p) ----
    float accO[8][4];
#pragma unroll
    for (int nt = 0; nt < 8; nt++)
#pragma unroll
        for (int e = 0; e < 4; e++) accO[nt][e] = 0.f;

#pragma unroll
    for (int kp = 0; kp < 8; kp++) {
        uint32_t vbase = (uint32_t)(kp >> 2) * 8192;
        int kl = kp & 3;
#pragma unroll
        for (int nt2 = 0; nt2 < 4; nt2++) {
            int r = nt2 * 16 + brow;
            uint32_t boff = vbase + (uint32_t)r * 128
                          + ((uint32_t)((kl * 2 + bsel) ^ (r & 7)) << 4);
            uint32_t bH[4], bL[4];
            ldsm_x4(bH, sb + AT_VH + boff);
            ldsm_x4(bL, sb + AT_VL + boff);
            mma_bf16(accO[2 * nt2],     wH[kp], bH);
            mma_bf16(accO[2 * nt2 + 1], wH[kp], bH + 2);
            mma_bf16(accO[2 * nt2],     wL[kp], bH);
            mma_bf16(accO[2 * nt2 + 1], wL[kp], bH + 2);
            mma_bf16(accO[2 * nt2],     wH[kp], bL);
            mma_bf16(accO[2 * nt2 + 1], wH[kp], bL + 2);
        }
    }

    // ---- epilogue: write O as bf16 hi/lo into the final GEMM's A buffers ----
    {
        long row0 = (long)(b * 4096 + lbase + w * 16 + (lane >> 2));
        int col = h * 64 + (lane & 3) * 2;
#pragma unroll
        for (int nt = 0; nt < 8; nt++) {
            long o0 = row0 * 1024 + col + nt * 8;
            long o1 = (row0 + 8) * 1024 + col + nt * 8;
            *(uint32_t*)(Oh + o0) = pack_hi(accO[nt][0], accO[nt][1]);
            *(uint32_t*)(Ol + o0) = pack_lo(accO[nt][0], accO[nt][1]);
            *(uint32_t*)(Oh + o1) = pack_hi(accO[nt][2], accO[nt][3]);
            *(uint32_t*)(Ol + o1) = pack_lo(accO[nt][2], accO[nt][3]);
        }
    }
}

// ---------------- launch ----------------
extern "C" void kernel_launch(void* const* d_in, const int* in_sizes, int n_in,
                              void* d_out, int out_size)
{
    const float* x    = (const float*)d_in[0];
    const float* fcos = (const float*)d_in[1];
    const float* fsin = (const float*)d_in[2];
    const float* Wq   = (const float*)d_in[3];
    const float* Wk   = (const float*)d_in[4];
    const float* Wv   = (const float*)d_in[5];
    const float* Wo   = (const float*)d_in[6];
    const float* kpm  = (const float*)d_in[7];
    const float* vpm  = (const float*)d_in[8];
    float* out = (float*)d_out;

    float *pQ, *pK, *pV;
    cudaGetSymbolAddress((void**)&pQ, g_Q);
    cudaGetSymbolAddress((void**)&pK, g_K);
    cudaGetSymbolAddress((void**)&pV, g_V);
    __nv_bfloat16 *pAh, *pAl, *pWqh, *pWql, *pWoh, *pWol, *pKPh, *pKPl, *pVTh, *pVTl;
    cudaGetSymbolAddress((void**)&pAh,  g_Ah);
    cudaGetSymbolAddress((void**)&pAl,  g_Al);
    cudaGetSymbolAddress((void**)&pWqh, g_Wqh);
    cudaGetSymbolAddress((void**)&pWql, g_Wql);
    cudaGetSymbolAddress((void**)&pWoh, g_Woh);
    cudaGetSymbolAddress((void**)&pWol, g_Wol);
    cudaGetSymbolAddress((void**)&pKPh, g_KPh);
    cudaGetSymbolAddress((void**)&pKPl, g_KPl);
    cudaGetSymbolAddress((void**)&pVTh, g_VTh);
    cudaGetSymbolAddress((void**)&pVTl, g_VTl);

    cudaFuncSetAttribute(hmma_gemm2, cudaFuncAttributeMaxDynamicSharedMemorySize, HG2_SMEM);
    cudaFuncSetAttribute(attn_hmma, cudaFuncAttributeMaxDynamicSharedMemorySize, AT_SMEM);

    // hi/lo splits of x, Wq, Wo
    cvt_hilo<<<16384, 256>>>(x, pAh, pAl);
    cvt_hilo<<<1024, 256>>>(Wq, pWqh, pWql);
    cvt_hilo<<<1024, 256>>>(Wo, pWoh, pWol);

    // Q = x @ Wq^T via pipelined HMMA
    {
        dim3 grid(8, 128, 1);
        hmma_gemm2<<<grid, 256, HG2_SMEM>>>(pAh, pAl, pWqh, pWql, pQ);
    }
    // K,V for first 128 rows of each batch (small, fp32 SGEMM)
    {
        dim3 grid(8, 4, 2);
        sgemm_tn<<<grid, 256>>>(x, Wk, pK, Wv, pV, 4194304L);
    }
    // K_proj / V_proj (RoPE on K inside), emitted as bf16 hi/lo
    proj_kernel<<<64, 128>>>(pK, pV, kpm, vpm, fcos, fsin, pKPh, pKPl, pVTh, pVTl);
    // HMMA flash attention -> writes O hi/lo straight into g_Ah/g_Al
    {
        dim3 grid(32, 64, 1);
        attn_hmma<<<grid, 256, AT_SMEM>>>(pQ, pKPh, pKPl, pVTh, pVTl, fcos, fsin, pAh, pAl);
    }
    // out = O @ Wo^T via pipelined HMMA
    {
        dim3 grid(8, 128, 1);
        hmma_gemm2<<<grid, 256, HG2_SMEM>>>(pAh, pAl, pWoh, pWol, out);
    }
}